// round 10
// baseline (speedup 1.0000x reference)
#include <cuda_runtime.h>
#include <cuda_fp16.h>
#include <math.h>
#include <stdint.h>

#define N_ENT  50000
#define N_PAD  50048           // 391 * 128
#define N_EDGE 500000
#define H      128
#define N_RELT 475

// ================= scratch (static __device__, zero-init at load) =========
// g_deg and g_base are re-zeroed by k_gemm3 at the end of every call.
__device__ int      g_deg[N_ENT];
__device__ int      g_off[N_ENT];
__device__ int      g_cur[N_ENT];
__device__ int      g_base;
__device__ unsigned g_pk[N_EDGE];        // packed src*512 + rel_id
__device__ __align__(16) __half g_ent16[N_ENT * H];    // fp16 copy of ent (12.8 MB)
__device__ __align__(16) __half g_rel16[N_RELT * H];   // fp16 copy of rel
__device__ __align__(16) __half g_a[3][N_PAD * H];     // neigh fp16 (pad rows stay 0)
__device__ __align__(16) __half g_wt[3][H * H];        // W^T fp16 (h-major rows)

// ================= helpers =================
__device__ __forceinline__ float fast_tanh(float x) {
    float e = __expf(2.f * x);
    return 1.f - __fdividef(2.f, e + 1.f);
}
__device__ __forceinline__ uint32_t smem_u32(const void* p) {
    uint32_t a;
    asm("{ .reg .u64 t; cvta.to.shared.u64 t, %1; cvt.u32.u64 %0, t; }" : "=r"(a) : "l"(p));
    return a;
}
#define LDSM4(R0, R1, R2, R3, addr) \
    asm volatile("ldmatrix.sync.aligned.m8n8.x4.shared.b16 {%0,%1,%2,%3}, [%4];" \
        : "=r"(R0), "=r"(R1), "=r"(R2), "=r"(R3) : "r"(addr))
#define MMA16816(C, A0, A1, A2, A3, B0, B1) \
    asm volatile("mma.sync.aligned.m16n8k16.row.col.f32.f16.f16.f32 " \
        "{%0,%1,%2,%3}, {%4,%5,%6,%7}, {%8,%9}, {%0,%1,%2,%3};" \
        : "+f"((C)[0]), "+f"((C)[1]), "+f"((C)[2]), "+f"((C)[3]) \
        : "r"(A0), "r"(A1), "r"(A2), "r"(A3), "r"(B0), "r"(B1))
#define CP16(sm_addr, gptr) \
    asm volatile("cp.async.cg.shared.global [%0], [%1], 16;" :: "r"(sm_addr), "l"(gptr))
#define CP_COMMIT() asm volatile("cp.async.commit_group;")
#define CP_WAIT0()  asm volatile("cp.async.wait_group 0;")

// ================= K1: degree histogram + fp16 table conversion ==========
// Conversion is independent elementwise work fused into the same grid.
__global__ void k_hist(const float* __restrict__ ent, const float* __restrict__ rel,
                       const int* __restrict__ dst) {
    int e = blockIdx.x * blockDim.x + threadIdx.x;
    if (e < N_EDGE) atomicAdd(&g_deg[dst[e]], 1);

    // ent: 6.4M floats = 400000 chunks of 16
    if (e < (N_ENT * H) / 16) {
        const float4* s = (const float4*)ent + (size_t)e * 4;
        float4 f0 = s[0], f1 = s[1], f2 = s[2], f3 = s[3];
        __half2 hh[8];
        hh[0] = __floats2half2_rn(f0.x, f0.y); hh[1] = __floats2half2_rn(f0.z, f0.w);
        hh[2] = __floats2half2_rn(f1.x, f1.y); hh[3] = __floats2half2_rn(f1.z, f1.w);
        hh[4] = __floats2half2_rn(f2.x, f2.y); hh[5] = __floats2half2_rn(f2.z, f2.w);
        hh[6] = __floats2half2_rn(f3.x, f3.y); hh[7] = __floats2half2_rn(f3.z, f3.w);
        uint4* d = (uint4*)(g_ent16 + (size_t)e * 16);
        d[0] = *(uint4*)&hh[0];
        d[1] = *(uint4*)&hh[4];
    }
    // rel: 60800 floats = 3800 chunks of 16, handled by threads [400000, 403800)
    int r = e - (N_ENT * H) / 16;
    if (r >= 0 && r < (N_RELT * H) / 16) {
        const float4* s = (const float4*)rel + (size_t)r * 4;
        float4 f0 = s[0], f1 = s[1], f2 = s[2], f3 = s[3];
        __half2 hh[8];
        hh[0] = __floats2half2_rn(f0.x, f0.y); hh[1] = __floats2half2_rn(f0.z, f0.w);
        hh[2] = __floats2half2_rn(f1.x, f1.y); hh[3] = __floats2half2_rn(f1.z, f1.w);
        hh[4] = __floats2half2_rn(f2.x, f2.y); hh[5] = __floats2half2_rn(f2.z, f2.w);
        hh[6] = __floats2half2_rn(f3.x, f3.y); hh[7] = __floats2half2_rn(f3.z, f3.w);
        uint4* d = (uint4*)(g_rel16 + (size_t)r * 16);
        d[0] = *(uint4*)&hh[0];
        d[1] = *(uint4*)&hh[4];
    }
}

// ================= K2: parallel CSR allocation + W^T fp16 prep ===========
__global__ void __launch_bounds__(256)
k_alloc(const float* __restrict__ we, const float* __restrict__ wn,
        const float* __restrict__ wc) {
    int t = threadIdx.x;
    int i = blockIdx.x * 256 + t;

    if (i < 3 * H * H) {
        int l = i >> 14, r = i & 16383;
        int k = r >> 7, h = r & 127;
        const float* W = (l == 0) ? we : (l == 1) ? wn : wc;
        g_wt[l][h * H + k] = __float2half(W[k * H + h]);
    }

    int d = (i < N_ENT) ? g_deg[i] : 0;
    int lane = t & 31, wid = t >> 5;
    int x = d;
    #pragma unroll
    for (int o = 1; o < 32; o <<= 1) {
        int y = __shfl_up_sync(0xffffffffu, x, o);
        if (lane >= o) x += y;
    }
    __shared__ int wsum[8];
    __shared__ int blockbase;
    if (lane == 31) wsum[wid] = x;
    __syncthreads();
    if (t == 0) {
        int run = 0;
        #pragma unroll
        for (int k = 0; k < 8; k++) { int v = wsum[k]; wsum[k] = run; run += v; }
        blockbase = atomicAdd(&g_base, run);
    }
    __syncthreads();
    if (i < N_ENT) {
        int excl = blockbase + wsum[wid] + (x - d);
        g_off[i] = excl;
        g_cur[i] = excl;
    }
}

// ================= K3: dst-grouped edge lists =================
__global__ void k_fill(const int* __restrict__ src, const int* __restrict__ dst,
                       const int* __restrict__ rid) {
    int e = blockIdx.x * blockDim.x + threadIdx.x;
    if (e >= N_EDGE) return;
    int p = atomicAdd(&g_cur[dst[e]], 1);
    g_pk[p] = (unsigned)src[e] * 512u + (unsigned)rid[e];
}

// ================= K4: warp-per-node fused agg (fp16 gathers) ============
// u/r gathered fp16 (8B/lane vs 16B): halves L1 wavefronts + L2 bytes.
__global__ void __launch_bounds__(256)
k_agg(const float* __restrict__ ent) {
    int w    = (blockIdx.x * blockDim.x + threadIdx.x) >> 5;
    int lane = threadIdx.x & 31;
    if (w >= N_ENT) return;

    float4 v = ((const float4*)(ent + (size_t)w * H))[lane];   // key row fp32
    int start = g_off[w];
    int end   = start + g_deg[w];

    float4 a0 = make_float4(0.f, 0.f, 0.f, 0.f), a1 = a0, a2 = a0;
    float s0 = 0.f, s1 = 0.f, s2 = 0.f;

    unsigned nA = 0, nB = 0;
    if (start < end) {
        nA = g_pk[start];
        nB = (start + 1 < end) ? g_pk[start + 1] : nA;
    }
    for (int i = start; i < end; i += 2) {
        unsigned pA = nA, pB = nB;
        int hasB = (i + 1 < end);
        int j = i + 2;
        if (j < end) {
            nA = g_pk[j];
            nB = (j + 1 < end) ? g_pk[j + 1] : nA;
        }

        uint2 ruA = ((const uint2*)(g_ent16 + (size_t)(pA >> 9) * H))[lane];
        uint2 rqA = ((const uint2*)(g_rel16 + (size_t)(pA & 511u) * H))[lane];
        uint2 ruB = ((const uint2*)(g_ent16 + (size_t)(pB >> 9) * H))[lane];
        uint2 rqB = ((const uint2*)(g_rel16 + (size_t)(pB & 511u) * H))[lane];

        float2 uA01 = __half22float2(*(__half2*)&ruA.x);
        float2 uA23 = __half22float2(*(__half2*)&ruA.y);
        float2 qA01 = __half22float2(*(__half2*)&rqA.x);
        float2 qA23 = __half22float2(*(__half2*)&rqA.y);
        float2 uB01 = __half22float2(*(__half2*)&ruB.x);
        float2 uB23 = __half22float2(*(__half2*)&ruB.y);
        float2 qB01 = __half22float2(*(__half2*)&rqB.x);
        float2 qB23 = __half22float2(*(__half2*)&rqB.y);

        float dnA = uA01.x * v.x + uA01.y * v.y + uA23.x * v.z + uA23.y * v.w;
        float deA = qA01.x * v.x + qA01.y * v.y + qA23.x * v.z + qA23.y * v.w;
        float dnB = uB01.x * v.x + uB01.y * v.y + uB23.x * v.z + uB23.y * v.w;
        float deB = qB01.x * v.x + qB01.y * v.y + qB23.x * v.z + qB23.y * v.w;
        #pragma unroll
        for (int o = 16; o; o >>= 1) {
            dnA += __shfl_xor_sync(0xffffffffu, dnA, o);
            deA += __shfl_xor_sync(0xffffffffu, deA, o);
            dnB += __shfl_xor_sync(0xffffffffu, dnB, o);
            deB += __shfl_xor_sync(0xffffffffu, deB, o);
        }
        float eA = __expf(deA), nAx = __expf(dnA), cA = eA * nAx;
        s0 += eA; s1 += nAx; s2 += cA;
        a0.x += eA * qA01.x; a0.y += eA * qA01.y; a0.z += eA * qA23.x; a0.w += eA * qA23.y;
        a1.x += nAx * uA01.x; a1.y += nAx * uA01.y; a1.z += nAx * uA23.x; a1.w += nAx * uA23.y;
        a2.x += cA * (uA01.x + qA01.x); a2.y += cA * (uA01.y + qA01.y);
        a2.z += cA * (uA23.x + qA23.x); a2.w += cA * (uA23.y + qA23.y);
        if (hasB) {
            float eB = __expf(deB), nBx = __expf(dnB), cB = eB * nBx;
            s0 += eB; s1 += nBx; s2 += cB;
            a0.x += eB * qB01.x; a0.y += eB * qB01.y; a0.z += eB * qB23.x; a0.w += eB * qB23.y;
            a1.x += nBx * uB01.x; a1.y += nBx * uB01.y; a1.z += nBx * uB23.x; a1.w += nBx * uB23.y;
            a2.x += cB * (uB01.x + qB01.x); a2.y += cB * (uB01.y + qB01.y);
            a2.z += cB * (uB23.x + qB23.x); a2.w += cB * (uB23.y + qB23.y);
        }
    }

    float i0 = (end > start) ? 1.f / s0 : 0.f;
    float i1 = (end > start) ? 1.f / s1 : 0.f;
    float i2 = (end > start) ? 1.f / s2 : 0.f;
    size_t off = (size_t)w * H + lane * 4;
    *(__half2*)&g_a[0][off]     = __floats2half2_rn(a0.x * i0, a0.y * i0);
    *(__half2*)&g_a[0][off + 2] = __floats2half2_rn(a0.z * i0, a0.w * i0);
    *(__half2*)&g_a[1][off]     = __floats2half2_rn(a1.x * i1, a1.y * i1);
    *(__half2*)&g_a[1][off + 2] = __floats2half2_rn(a1.z * i1, a1.w * i1);
    *(__half2*)&g_a[2][off]     = __floats2half2_rn(a2.x * i2, a2.y * i2);
    *(__half2*)&g_a[2][off + 2] = __floats2half2_rn(a2.z * i2, a2.w * i2);
}

// ================= K5: fp16 HMMA GEMM, A double-buffered via cp.async =====
#define PITCH    272
#define TILE_B   (128 * PITCH)          // 34816
#define SM_A0    0
#define SM_A1    TILE_B
#define SM_W     (2 * TILE_B)
#define SM_TOT   (3 * TILE_B)           // 104448

__device__ __forceinline__ void fill_tile_async(uint32_t smbase, const uint4* src, int tid) {
    #pragma unroll
    for (int i = 0; i < 8; i++) {
        int idx = i * 256 + tid;
        int row = idx >> 4, ch = idx & 15;
        CP16(smbase + (uint32_t)(row * PITCH + ch * 16), src + idx);
    }
}

__global__ void __launch_bounds__(256, 2)
k_gemm3(const float* __restrict__ ent, float* __restrict__ out) {
    extern __shared__ char sm[];
    uint32_t sb = smem_u32(sm);
    int tid  = threadIdx.x;
    int wid  = tid >> 5;
    int lane = tid & 31;
    int row0 = blockIdx.x * 128;

    // re-zero scratch for next graph replay (g_deg dead after k_agg)
    int z = blockIdx.x * 256 + tid;
    if (z < N_ENT) g_deg[z] = 0;
    if (z == N_ENT) g_base = 0;

    int q = lane >> 3, r = lane & 7;
    uint32_t a_off = (uint32_t)((wid * 16 + r + (q & 1) * 8) * PITCH + (q >> 1) * 16);
    uint32_t b_off = (uint32_t)(((q >> 1) * 8 + r) * PITCH + (q & 1) * 16);

    fill_tile_async(sb + SM_A0, (const uint4*)(g_a[0] + (size_t)row0 * H), tid);
    fill_tile_async(sb + SM_W,  (const uint4*)(g_wt[0]), tid);
    CP_COMMIT();
    CP_WAIT0();
    __syncthreads();

    int cur = 0;
    for (int layer = 0; layer < 3; layer++) {
        if (layer < 2) {
            fill_tile_async(sb + (cur ? SM_A0 : SM_A1),
                            (const uint4*)(g_a[layer + 1] + (size_t)row0 * H), tid);
            CP_COMMIT();
        }

        float c[16][4];
        #pragma unroll
        for (int nt = 0; nt < 16; nt++)
            #pragma unroll
            for (int j = 0; j < 4; j++) c[nt][j] = 0.f;

        uint32_t ab = sb + (cur ? SM_A1 : SM_A0) + a_off;
        uint32_t bb = sb + SM_W + b_off;
        #pragma unroll
        for (int ks = 0; ks < 8; ks++) {
            uint32_t aa0, aa1, aa2, aa3;
            LDSM4(aa0, aa1, aa2, aa3, ab + ks * 32);
            #pragma unroll
            for (int np = 0; np < 8; np++) {
                uint32_t b0, b1, b2, b3;
                LDSM4(b0, b1, b2, b3, bb + np * (16 * PITCH) + ks * 32);
                MMA16816(c[np * 2],     aa0, aa1, aa2, aa3, b0, b1);
                MMA16816(c[np * 2 + 1], aa0, aa1, aa2, aa3, b2, b3);
            }
        }

        int m0 = row0 + wid * 16 + (lane >> 2);
        int nb = (lane & 3) * 2;
        #pragma unroll
        for (int nt = 0; nt < 16; nt++) {
            int n = nt * 8 + nb;
            if (m0 < N_ENT) {
                float2* p = (float2*)(out + (size_t)m0 * H + n);
                float2 v0 = (layer == 0)
                    ? *(const float2*)(ent + (size_t)m0 * H + n) : *p;
                v0.x += fast_tanh(c[nt][0]);
                v0.y += fast_tanh(c[nt][1]);
                *p = v0;
            }
            if (m0 + 8 < N_ENT) {
                float2* p = (float2*)(out + (size_t)(m0 + 8) * H + n);
                float2 v1 = (layer == 0)
                    ? *(const float2*)(ent + (size_t)(m0 + 8) * H + n) : *p;
                v1.x += fast_tanh(c[nt][2]);
                v1.y += fast_tanh(c[nt][3]);
                *p = v1;
            }
        }
        __syncthreads();
        if (layer < 2) {
            fill_tile_async(sb + SM_W, (const uint4*)(g_wt[layer + 1]), tid);
            CP_COMMIT();
            CP_WAIT0();
            __syncthreads();
            cur ^= 1;
        }
    }
}

// ================= launch =================
extern "C" void kernel_launch(void* const* d_in, const int* in_sizes, int n_in,
                              void* d_out, int out_size) {
    const float* ent    = (const float*)d_in[0];
    const float* rel    = (const float*)d_in[1];
    const float* w_edge = (const float*)d_in[2];
    const float* w_node = (const float*)d_in[3];
    const float* w_comp = (const float*)d_in[4];
    const int*   src    = (const int*)d_in[5];
    const int*   dst    = (const int*)d_in[6];
    const int*   rid    = (const int*)d_in[7];
    float*       out    = (float*)d_out;

    cudaFuncSetAttribute(k_gemm3, cudaFuncAttributeMaxDynamicSharedMemorySize, SM_TOT);

    // g_deg/g_base are zero at load and re-zeroed by k_gemm3 every call.
    k_hist <<<(N_EDGE + 255) / 256, 256>>>(ent, rel, dst);   // launch 1 (+fp16 conv)
    k_alloc<<<196, 256>>>(w_edge, w_node, w_comp);           // launch 2
    k_fill <<<(N_EDGE + 255) / 256, 256>>>(src, dst, rid);   // launch 3
    k_agg  <<<N_ENT / 8, 256>>>(ent);                        // launch 4 <- profiled
    k_gemm3<<<N_PAD / 128, 256, SM_TOT>>>(ent, out);         // launch 5
}

// round 11
// speedup vs baseline: 1.0361x; 1.0361x over previous
#include <cuda_runtime.h>
#include <cuda_fp16.h>
#include <math.h>
#include <stdint.h>

#define N_ENT  50000
#define N_PAD  50048           // 391 * 128
#define N_EDGE 500000
#define H      128

// ================= scratch (static __device__, zero-init at load) =========
// g_deg, g_dh, g_base are re-zeroed by k_gemm3 at the end of every call.
__device__ int      g_deg[N_ENT];
__device__ int      g_off[N_ENT];
__device__ int      g_cur[N_ENT];
__device__ int      g_base;
__device__ int      g_dh[64];            // degree histogram (clamped bins)
__device__ int      g_dcur[64];          // bin cursors (rebuilt by k_rank)
__device__ int      g_perm[N_ENT];       // degree-sorted node order
__device__ unsigned g_pk[N_EDGE];        // packed src*512 + rel_id
__device__ __align__(16) __half g_a[3][N_PAD * H];   // neigh fp16 (pad rows stay 0)
__device__ __align__(16) __half g_wt[3][H * H];      // W^T fp16 (h-major rows)

// ================= helpers =================
__device__ __forceinline__ float dot4(float4 a, float4 b) {
    return a.x * b.x + a.y * b.y + a.z * b.z + a.w * b.w;
}
__device__ __forceinline__ float fast_tanh(float x) {
    float e = __expf(2.f * x);
    return 1.f - __fdividef(2.f, e + 1.f);
}
__device__ __forceinline__ uint32_t smem_u32(const void* p) {
    uint32_t a;
    asm("{ .reg .u64 t; cvta.to.shared.u64 t, %1; cvt.u32.u64 %0, t; }" : "=r"(a) : "l"(p));
    return a;
}
#define LDSM4(R0, R1, R2, R3, addr) \
    asm volatile("ldmatrix.sync.aligned.m8n8.x4.shared.b16 {%0,%1,%2,%3}, [%4];" \
        : "=r"(R0), "=r"(R1), "=r"(R2), "=r"(R3) : "r"(addr))
#define MMA16816(C, A0, A1, A2, A3, B0, B1) \
    asm volatile("mma.sync.aligned.m16n8k16.row.col.f32.f16.f16.f32 " \
        "{%0,%1,%2,%3}, {%4,%5,%6,%7}, {%8,%9}, {%0,%1,%2,%3};" \
        : "+f"((C)[0]), "+f"((C)[1]), "+f"((C)[2]), "+f"((C)[3]) \
        : "r"(A0), "r"(A1), "r"(A2), "r"(A3), "r"(B0), "r"(B1))
#define CP16(sm_addr, gptr) \
    asm volatile("cp.async.cg.shared.global [%0], [%1], 16;" :: "r"(sm_addr), "l"(gptr))
#define CP_COMMIT() asm volatile("cp.async.commit_group;")
#define CP_WAIT0()  asm volatile("cp.async.wait_group 0;")

// ================= K1: degree histogram =================
__global__ void k_hist(const int* __restrict__ dst) {
    int e = blockIdx.x * blockDim.x + threadIdx.x;
    if (e < N_EDGE) atomicAdd(&g_deg[dst[e]], 1);
}

// ================= K2: CSR offsets + W^T fp16 + degree-bin histogram =====
__global__ void __launch_bounds__(256)
k_alloc(const float* __restrict__ we, const float* __restrict__ wn,
        const float* __restrict__ wc) {
    int t = threadIdx.x;
    int i = blockIdx.x * 256 + t;

    if (i < 3 * H * H) {
        int l = i >> 14, r = i & 16383;
        int k = r >> 7, h = r & 127;
        const float* W = (l == 0) ? we : (l == 1) ? wn : wc;
        g_wt[l][h * H + k] = __float2half(W[k * H + h]);
    }

    int d = (i < N_ENT) ? g_deg[i] : 0;

    // degree-bin histogram (warp-aggregated atomics)
    unsigned act = __ballot_sync(0xffffffffu, i < N_ENT);
    if (i < N_ENT) {
        int bin = d < 63 ? d : 63;
        unsigned mask = __match_any_sync(act, bin);
        int leader = __ffs(mask) - 1;
        int lane = t & 31;
        if (lane == leader) atomicAdd(&g_dh[bin], __popc(mask));
    }

    // block-local scan + one atomic for segment base
    int lane = t & 31, wid = t >> 5;
    int x = d;
    #pragma unroll
    for (int o = 1; o < 32; o <<= 1) {
        int y = __shfl_up_sync(0xffffffffu, x, o);
        if (lane >= o) x += y;
    }
    __shared__ int wsum[8];
    __shared__ int blockbase;
    if (lane == 31) wsum[wid] = x;
    __syncthreads();
    if (t == 0) {
        int run = 0;
        #pragma unroll
        for (int k = 0; k < 8; k++) { int v = wsum[k]; wsum[k] = run; run += v; }
        blockbase = atomicAdd(&g_base, run);
    }
    __syncthreads();
    if (i < N_ENT) {
        int excl = blockbase + wsum[wid] + (x - d);
        g_off[i] = excl;
        g_cur[i] = excl;
    }
}

// ================= K3: 64-bin exclusive prefix -> bin cursors ============
__global__ void k_rank() {
    if (threadIdx.x == 0) {
        int run = 0;
        #pragma unroll
        for (int b = 0; b < 64; b++) { int c = g_dh[b]; g_dcur[b] = run; run += c; }
    }
}

// ================= K4: edge scatter + degree-sorted permutation ==========
__global__ void k_fill(const int* __restrict__ src, const int* __restrict__ dst,
                       const int* __restrict__ rid) {
    int e = blockIdx.x * blockDim.x + threadIdx.x;
    if (e < N_EDGE) {
        int p = atomicAdd(&g_cur[dst[e]], 1);
        g_pk[p] = (unsigned)src[e] * 512u + (unsigned)rid[e];
    }
    // counting-sort scatter: rank nodes by degree (warp-aggregated)
    unsigned act = __ballot_sync(0xffffffffu, e < N_ENT);
    if (e < N_ENT) {
        int d = g_deg[e];
        int bin = d < 63 ? d : 63;
        unsigned mask = __match_any_sync(act, bin);
        int leader = __ffs(mask) - 1;
        int lane = threadIdx.x & 31;
        int base;
        if (lane == leader) base = atomicAdd(&g_dcur[bin], __popc(mask));
        base = __shfl_sync(mask, base, leader);
        int rank = base + __popc(mask & ((1u << lane) - 1u));
        g_perm[rank] = e;
    }
}

// ================= K5: warp-per-node fused agg (degree-sorted order) =====
// All 8 warps in a block now have equal (+-1) degree -> block retires at
// mean degree, not max-of-8.
__global__ void __launch_bounds__(256)
k_agg(const float* __restrict__ ent, const float* __restrict__ rel) {
    int slot = (blockIdx.x * blockDim.x + threadIdx.x) >> 5;
    int lane = threadIdx.x & 31;
    if (slot >= N_ENT) return;
    int w = g_perm[slot];

    float4 v = ((const float4*)(ent + (size_t)w * H))[lane];
    int start = g_off[w];
    int end   = start + g_deg[w];

    float4 a0 = make_float4(0.f, 0.f, 0.f, 0.f), a1 = a0, a2 = a0;
    float s0 = 0.f, s1 = 0.f, s2 = 0.f;

    unsigned nA = 0, nB = 0;
    if (start < end) {
        nA = g_pk[start];
        nB = (start + 1 < end) ? g_pk[start + 1] : nA;
    }
    for (int i = start; i < end; i += 2) {
        unsigned pA = nA, pB = nB;
        int hasB = (i + 1 < end);
        int j = i + 2;
        if (j < end) {
            nA = g_pk[j];
            nB = (j + 1 < end) ? g_pk[j + 1] : nA;
        }

        float4 uA = ((const float4*)(ent + (size_t)(pA >> 9) * H))[lane];
        float4 qA = ((const float4*)(rel + (size_t)(pA & 511u) * H))[lane];
        float4 uB = ((const float4*)(ent + (size_t)(pB >> 9) * H))[lane];
        float4 qB = ((const float4*)(rel + (size_t)(pB & 511u) * H))[lane];

        float dnA = dot4(uA, v), deA = dot4(qA, v);
        float dnB = dot4(uB, v), deB = dot4(qB, v);
        #pragma unroll
        for (int o = 16; o; o >>= 1) {
            dnA += __shfl_xor_sync(0xffffffffu, dnA, o);
            deA += __shfl_xor_sync(0xffffffffu, deA, o);
            dnB += __shfl_xor_sync(0xffffffffu, dnB, o);
            deB += __shfl_xor_sync(0xffffffffu, deB, o);
        }
        float eA = __expf(deA), nAx = __expf(dnA), cA = eA * nAx;
        s0 += eA; s1 += nAx; s2 += cA;
        a0.x += eA * qA.x; a0.y += eA * qA.y; a0.z += eA * qA.z; a0.w += eA * qA.w;
        a1.x += nAx * uA.x; a1.y += nAx * uA.y; a1.z += nAx * uA.z; a1.w += nAx * uA.w;
        a2.x += cA * (uA.x + qA.x); a2.y += cA * (uA.y + qA.y);
        a2.z += cA * (uA.z + qA.z); a2.w += cA * (uA.w + qA.w);
        if (hasB) {
            float eB = __expf(deB), nBx = __expf(dnB), cB = eB * nBx;
            s0 += eB; s1 += nBx; s2 += cB;
            a0.x += eB * qB.x; a0.y += eB * qB.y; a0.z += eB * qB.z; a0.w += eB * qB.w;
            a1.x += nBx * uB.x; a1.y += nBx * uB.y; a1.z += nBx * uB.z; a1.w += nBx * uB.w;
            a2.x += cB * (uB.x + qB.x); a2.y += cB * (uB.y + qB.y);
            a2.z += cB * (uB.z + qB.z); a2.w += cB * (uB.w + qB.w);
        }
    }

    float i0 = (end > start) ? 1.f / s0 : 0.f;
    float i1 = (end > start) ? 1.f / s1 : 0.f;
    float i2 = (end > start) ? 1.f / s2 : 0.f;
    size_t off = (size_t)w * H + lane * 4;
    *(__half2*)&g_a[0][off]     = __floats2half2_rn(a0.x * i0, a0.y * i0);
    *(__half2*)&g_a[0][off + 2] = __floats2half2_rn(a0.z * i0, a0.w * i0);
    *(__half2*)&g_a[1][off]     = __floats2half2_rn(a1.x * i1, a1.y * i1);
    *(__half2*)&g_a[1][off + 2] = __floats2half2_rn(a1.z * i1, a1.w * i1);
    *(__half2*)&g_a[2][off]     = __floats2half2_rn(a2.x * i2, a2.y * i2);
    *(__half2*)&g_a[2][off + 2] = __floats2half2_rn(a2.z * i2, a2.w * i2);
}

// ================= K6: fp16 HMMA GEMM, A double-buffered via cp.async =====
#define PITCH    272
#define TILE_B   (128 * PITCH)          // 34816
#define SM_A0    0
#define SM_A1    TILE_B
#define SM_W     (2 * TILE_B)
#define SM_TOT   (3 * TILE_B)           // 104448

__device__ __forceinline__ void fill_tile_async(uint32_t smbase, const uint4* src, int tid) {
    #pragma unroll
    for (int i = 0; i < 8; i++) {
        int idx = i * 256 + tid;
        int row = idx >> 4, ch = idx & 15;
        CP16(smbase + (uint32_t)(row * PITCH + ch * 16), src + idx);
    }
}

__global__ void __launch_bounds__(256, 2)
k_gemm3(const float* __restrict__ ent, float* __restrict__ out) {
    extern __shared__ char sm[];
    uint32_t sb = smem_u32(sm);
    int tid  = threadIdx.x;
    int wid  = tid >> 5;
    int lane = tid & 31;
    int row0 = blockIdx.x * 128;

    // re-zero scratch for next graph replay (dead after k_agg)
    int z = blockIdx.x * 256 + tid;
    if (z < N_ENT) g_deg[z] = 0;
    if (z == N_ENT) g_base = 0;
    if (z >= N_ENT + 1 && z < N_ENT + 1 + 64) g_dh[z - N_ENT - 1] = 0;

    int q = lane >> 3, r = lane & 7;
    uint32_t a_off = (uint32_t)((wid * 16 + r + (q & 1) * 8) * PITCH + (q >> 1) * 16);
    uint32_t b_off = (uint32_t)(((q >> 1) * 8 + r) * PITCH + (q & 1) * 16);

    fill_tile_async(sb + SM_A0, (const uint4*)(g_a[0] + (size_t)row0 * H), tid);
    fill_tile_async(sb + SM_W,  (const uint4*)(g_wt[0]), tid);
    CP_COMMIT();
    CP_WAIT0();
    __syncthreads();

    int cur = 0;
    for (int layer = 0; layer < 3; layer++) {
        if (layer < 2) {
            fill_tile_async(sb + (cur ? SM_A0 : SM_A1),
                            (const uint4*)(g_a[layer + 1] + (size_t)row0 * H), tid);
            CP_COMMIT();
        }

        float c[16][4];
        #pragma unroll
        for (int nt = 0; nt < 16; nt++)
            #pragma unroll
            for (int j = 0; j < 4; j++) c[nt][j] = 0.f;

        uint32_t ab = sb + (cur ? SM_A1 : SM_A0) + a_off;
        uint32_t bb = sb + SM_W + b_off;
        #pragma unroll
        for (int ks = 0; ks < 8; ks++) {
            uint32_t aa0, aa1, aa2, aa3;
            LDSM4(aa0, aa1, aa2, aa3, ab + ks * 32);
            #pragma unroll
            for (int np = 0; np < 8; np++) {
                uint32_t b0, b1, b2, b3;
                LDSM4(b0, b1, b2, b3, bb + np * (16 * PITCH) + ks * 32);
                MMA16816(c[np * 2],     aa0, aa1, aa2, aa3, b0, b1);
                MMA16816(c[np * 2 + 1], aa0, aa1, aa2, aa3, b2, b3);
            }
        }

        int m0 = row0 + wid * 16 + (lane >> 2);
        int nb = (lane & 3) * 2;
        #pragma unroll
        for (int nt = 0; nt < 16; nt++) {
            int n = nt * 8 + nb;
            if (m0 < N_ENT) {
                float2* p = (float2*)(out + (size_t)m0 * H + n);
                float2 v0 = (layer == 0)
                    ? *(const float2*)(ent + (size_t)m0 * H + n) : *p;
                v0.x += fast_tanh(c[nt][0]);
                v0.y += fast_tanh(c[nt][1]);
                *p = v0;
            }
            if (m0 + 8 < N_ENT) {
                float2* p = (float2*)(out + (size_t)(m0 + 8) * H + n);
                float2 v1 = (layer == 0)
                    ? *(const float2*)(ent + (size_t)(m0 + 8) * H + n) : *p;
                v1.x += fast_tanh(c[nt][2]);
                v1.y += fast_tanh(c[nt][3]);
                *p = v1;
            }
        }
        __syncthreads();
        if (layer < 2) {
            fill_tile_async(sb + SM_W, (const uint4*)(g_wt[layer + 1]), tid);
            CP_COMMIT();
            CP_WAIT0();
            __syncthreads();
            cur ^= 1;
        }
    }
}

// ================= launch =================
extern "C" void kernel_launch(void* const* d_in, const int* in_sizes, int n_in,
                              void* d_out, int out_size) {
    const float* ent    = (const float*)d_in[0];
    const float* rel    = (const float*)d_in[1];
    const float* w_edge = (const float*)d_in[2];
    const float* w_node = (const float*)d_in[3];
    const float* w_comp = (const float*)d_in[4];
    const int*   src    = (const int*)d_in[5];
    const int*   dst    = (const int*)d_in[6];
    const int*   rid    = (const int*)d_in[7];
    float*       out    = (float*)d_out;

    cudaFuncSetAttribute(k_gemm3, cudaFuncAttributeMaxDynamicSharedMemorySize, SM_TOT);

    // g_deg/g_dh/g_base are zero at load and re-zeroed by k_gemm3 every call.
    k_hist <<<(N_EDGE + 255) / 256, 256>>>(dst);             // launch 1
    k_alloc<<<196, 256>>>(w_edge, w_node, w_comp);           // launch 2
    k_rank <<<1, 32>>>();                                    // launch 3
    k_fill <<<(N_EDGE + 255) / 256, 256>>>(src, dst, rid);   // launch 4
    k_agg  <<<N_ENT / 8, 256>>>(ent, rel);                   // launch 5
    k_gemm3<<<N_PAD / 128, 256, SM_TOT>>>(ent, out);         // launch 6
}

// round 12
// speedup vs baseline: 1.2688x; 1.2245x over previous
#include <cuda_runtime.h>
#include <cuda_fp16.h>
#include <math.h>
#include <stdint.h>

#define N_ENT  50000
#define N_PAD  50048           // 391 * 128
#define N_EDGE 500000
#define H      128

// ================= scratch (static __device__, zero-init at load) =========
// g_deg and g_base are re-zeroed by k_gemm3 at the end of every call.
__device__ int      g_deg[N_ENT];
__device__ int      g_off[N_ENT];
__device__ int      g_base;
__device__ int      g_rank[N_EDGE];      // edge rank within dst segment (from k_hist)
__device__ unsigned g_pk[N_EDGE];        // packed src*512 + rel_id
__device__ __align__(16) __half g_a[3][N_PAD * H];   // neigh fp16 (pad rows stay 0)
__device__ __align__(16) __half g_wt[3][H * H];      // W^T fp16 (h-major rows)

// ================= helpers =================
__device__ __forceinline__ float dot4(float4 a, float4 b) {
    return a.x * b.x + a.y * b.y + a.z * b.z + a.w * b.w;
}
__device__ __forceinline__ float fast_tanh(float x) {
    float e = __expf(2.f * x);
    return 1.f - __fdividef(2.f, e + 1.f);
}
__device__ __forceinline__ uint32_t smem_u32(const void* p) {
    uint32_t a;
    asm("{ .reg .u64 t; cvta.to.shared.u64 t, %1; cvt.u32.u64 %0, t; }" : "=r"(a) : "l"(p));
    return a;
}
#define LDSM4(R0, R1, R2, R3, addr) \
    asm volatile("ldmatrix.sync.aligned.m8n8.x4.shared.b16 {%0,%1,%2,%3}, [%4];" \
        : "=r"(R0), "=r"(R1), "=r"(R2), "=r"(R3) : "r"(addr))
#define MMA16816(C, A0, A1, A2, A3, B0, B1) \
    asm volatile("mma.sync.aligned.m16n8k16.row.col.f32.f16.f16.f32 " \
        "{%0,%1,%2,%3}, {%4,%5,%6,%7}, {%8,%9}, {%0,%1,%2,%3};" \
        : "+f"((C)[0]), "+f"((C)[1]), "+f"((C)[2]), "+f"((C)[3]) \
        : "r"(A0), "r"(A1), "r"(A2), "r"(A3), "r"(B0), "r"(B1))
#define CP16(sm_addr, gptr) \
    asm volatile("cp.async.cg.shared.global [%0], [%1], 16;" :: "r"(sm_addr), "l"(gptr))
#define CP_COMMIT() asm volatile("cp.async.commit_group;")
#define CP_WAIT0()  asm volatile("cp.async.wait_group 0;")

// ================= K1: degree histogram; atomic return = segment rank ====
__global__ void k_hist(const int* __restrict__ dst) {
    int e = blockIdx.x * blockDim.x + threadIdx.x;
    if (e < N_EDGE) g_rank[e] = atomicAdd(&g_deg[dst[e]], 1);
}

// ================= K2: parallel CSR offsets + W^T fp16 prep ==============
__global__ void __launch_bounds__(256)
k_alloc(const float* __restrict__ we, const float* __restrict__ wn,
        const float* __restrict__ wc) {
    int t = threadIdx.x;
    int i = blockIdx.x * 256 + t;

    if (i < 3 * H * H) {
        int l = i >> 14, r = i & 16383;
        int k = r >> 7, h = r & 127;
        const float* W = (l == 0) ? we : (l == 1) ? wn : wc;
        g_wt[l][h * H + k] = __float2half(W[k * H + h]);
    }

    int d = (i < N_ENT) ? g_deg[i] : 0;
    int lane = t & 31, wid = t >> 5;
    int x = d;
    #pragma unroll
    for (int o = 1; o < 32; o <<= 1) {
        int y = __shfl_up_sync(0xffffffffu, x, o);
        if (lane >= o) x += y;
    }
    __shared__ int wsum[8];
    __shared__ int blockbase;
    if (lane == 31) wsum[wid] = x;
    __syncthreads();
    if (t == 0) {
        int run = 0;
        #pragma unroll
        for (int k = 0; k < 8; k++) { int v = wsum[k]; wsum[k] = run; run += v; }
        blockbase = atomicAdd(&g_base, run);
    }
    __syncthreads();
    if (i < N_ENT) g_off[i] = blockbase + wsum[wid] + (x - d);
}

// ================= K3: atomic-free edge scatter ==========================
__global__ void k_fill(const int* __restrict__ src, const int* __restrict__ dst,
                       const int* __restrict__ rid) {
    int e = blockIdx.x * blockDim.x + threadIdx.x;
    if (e >= N_EDGE) return;
    int p = g_off[dst[e]] + g_rank[e];
    g_pk[p] = (unsigned)src[e] * 512u + (unsigned)rid[e];
}

// ================= K4: warp-per-node fused agg (R8 form) =================
__global__ void __launch_bounds__(256)
k_agg(const float* __restrict__ ent, const float* __restrict__ rel) {
    int w    = (blockIdx.x * blockDim.x + threadIdx.x) >> 5;
    int lane = threadIdx.x & 31;
    if (w >= N_ENT) return;

    float4 v = ((const float4*)(ent + (size_t)w * H))[lane];
    int start = g_off[w];
    int end   = start + g_deg[w];

    float4 a0 = make_float4(0.f, 0.f, 0.f, 0.f), a1 = a0, a2 = a0;
    float s0 = 0.f, s1 = 0.f, s2 = 0.f;

    unsigned nA = 0, nB = 0;
    if (start < end) {
        nA = g_pk[start];
        nB = (start + 1 < end) ? g_pk[start + 1] : nA;
    }
    for (int i = start; i < end; i += 2) {
        unsigned pA = nA, pB = nB;
        int hasB = (i + 1 < end);
        int j = i + 2;
        if (j < end) {
            nA = g_pk[j];
            nB = (j + 1 < end) ? g_pk[j + 1] : nA;
        }

        float4 uA = ((const float4*)(ent + (size_t)(pA >> 9) * H))[lane];
        float4 qA = ((const float4*)(rel + (size_t)(pA & 511u) * H))[lane];
        float4 uB = ((const float4*)(ent + (size_t)(pB >> 9) * H))[lane];
        float4 qB = ((const float4*)(rel + (size_t)(pB & 511u) * H))[lane];

        float dnA = dot4(uA, v), deA = dot4(qA, v);
        float dnB = dot4(uB, v), deB = dot4(qB, v);
        #pragma unroll
        for (int o = 16; o; o >>= 1) {
            dnA += __shfl_xor_sync(0xffffffffu, dnA, o);
            deA += __shfl_xor_sync(0xffffffffu, deA, o);
            dnB += __shfl_xor_sync(0xffffffffu, dnB, o);
            deB += __shfl_xor_sync(0xffffffffu, deB, o);
        }
        float eA = __expf(deA), nAx = __expf(dnA), cA = eA * nAx;
        s0 += eA; s1 += nAx; s2 += cA;
        a0.x += eA * qA.x; a0.y += eA * qA.y; a0.z += eA * qA.z; a0.w += eA * qA.w;
        a1.x += nAx * uA.x; a1.y += nAx * uA.y; a1.z += nAx * uA.z; a1.w += nAx * uA.w;
        a2.x += cA * (uA.x + qA.x); a2.y += cA * (uA.y + qA.y);
        a2.z += cA * (uA.z + qA.z); a2.w += cA * (uA.w + qA.w);
        if (hasB) {
            float eB = __expf(deB), nBx = __expf(dnB), cB = eB * nBx;
            s0 += eB; s1 += nBx; s2 += cB;
            a0.x += eB * qB.x; a0.y += eB * qB.y; a0.z += eB * qB.z; a0.w += eB * qB.w;
            a1.x += nBx * uB.x; a1.y += nBx * uB.y; a1.z += nBx * uB.z; a1.w += nBx * uB.w;
            a2.x += cB * (uB.x + qB.x); a2.y += cB * (uB.y + qB.y);
            a2.z += cB * (uB.z + qB.z); a2.w += cB * (uB.w + qB.w);
        }
    }

    float i0 = (end > start) ? 1.f / s0 : 0.f;
    float i1 = (end > start) ? 1.f / s1 : 0.f;
    float i2 = (end > start) ? 1.f / s2 : 0.f;
    size_t off = (size_t)w * H + lane * 4;
    *(__half2*)&g_a[0][off]     = __floats2half2_rn(a0.x * i0, a0.y * i0);
    *(__half2*)&g_a[0][off + 2] = __floats2half2_rn(a0.z * i0, a0.w * i0);
    *(__half2*)&g_a[1][off]     = __floats2half2_rn(a1.x * i1, a1.y * i1);
    *(__half2*)&g_a[1][off + 2] = __floats2half2_rn(a1.z * i1, a1.w * i1);
    *(__half2*)&g_a[2][off]     = __floats2half2_rn(a2.x * i2, a2.y * i2);
    *(__half2*)&g_a[2][off + 2] = __floats2half2_rn(a2.z * i2, a2.w * i2);
}

// ================= K5: fp16 HMMA GEMM, cross-layer register accumulator ===
// out touched exactly once: out = ent + sum_layers tanh(A_l @ W_l).
// N-range split in two half-passes per layer to keep c small (regs: acc 64 + c 32).
#define PITCH    272
#define TILE_B   (128 * PITCH)          // 34816
#define SM_A0    0
#define SM_A1    TILE_B
#define SM_W     (2 * TILE_B)
#define SM_TOT   (3 * TILE_B)           // 104448

__device__ __forceinline__ void fill_tile_async(uint32_t smbase, const uint4* src, int tid) {
    #pragma unroll
    for (int i = 0; i < 8; i++) {
        int idx = i * 256 + tid;
        int row = idx >> 4, ch = idx & 15;
        CP16(smbase + (uint32_t)(row * PITCH + ch * 16), src + idx);
    }
}

__global__ void __launch_bounds__(256, 2)
k_gemm3(const float* __restrict__ ent, float* __restrict__ out) {
    extern __shared__ char sm[];
    uint32_t sb = smem_u32(sm);
    int tid  = threadIdx.x;
    int wid  = tid >> 5;
    int lane = tid & 31;
    int row0 = blockIdx.x * 128;

    // re-zero scratch for next graph replay (dead after k_agg)
    int z = blockIdx.x * 256 + tid;
    if (z < N_ENT) g_deg[z] = 0;
    if (z == N_ENT) g_base = 0;

    int q = lane >> 3, r = lane & 7;
    uint32_t a_off = (uint32_t)((wid * 16 + r + (q & 1) * 8) * PITCH + (q >> 1) * 16);
    uint32_t b_off = (uint32_t)(((q >> 1) * 8 + r) * PITCH + (q & 1) * 16);

    fill_tile_async(sb + SM_A0, (const uint4*)(g_a[0] + (size_t)row0 * H), tid);
    fill_tile_async(sb + SM_W,  (const uint4*)(g_wt[0]), tid);
    CP_COMMIT();
    CP_WAIT0();
    __syncthreads();

    float acc[16][4];
    #pragma unroll
    for (int nt = 0; nt < 16; nt++)
        #pragma unroll
        for (int j = 0; j < 4; j++) acc[nt][j] = 0.f;

    int cur = 0;
    for (int layer = 0; layer < 3; layer++) {
        if (layer < 2) {
            fill_tile_async(sb + (cur ? SM_A0 : SM_A1),
                            (const uint4*)(g_a[layer + 1] + (size_t)row0 * H), tid);
            CP_COMMIT();
        }

        uint32_t ab = sb + (cur ? SM_A1 : SM_A0) + a_off;
        uint32_t bb = sb + SM_W + b_off;

        #pragma unroll
        for (int nh = 0; nh < 2; nh++) {
            float c[8][4];
            #pragma unroll
            for (int nt = 0; nt < 8; nt++)
                #pragma unroll
                for (int j = 0; j < 4; j++) c[nt][j] = 0.f;

            #pragma unroll
            for (int ks = 0; ks < 8; ks++) {
                uint32_t aa0, aa1, aa2, aa3;
                LDSM4(aa0, aa1, aa2, aa3, ab + ks * 32);
                #pragma unroll
                for (int np = 0; np < 4; np++) {
                    uint32_t b0, b1, b2, b3;
                    LDSM4(b0, b1, b2, b3,
                          bb + (nh * 4 + np) * (16 * PITCH) + ks * 32);
                    MMA16816(c[np * 2],     aa0, aa1, aa2, aa3, b0, b1);
                    MMA16816(c[np * 2 + 1], aa0, aa1, aa2, aa3, b2, b3);
                }
            }
            #pragma unroll
            for (int nt = 0; nt < 8; nt++)
                #pragma unroll
                for (int j = 0; j < 4; j++)
                    acc[nh * 8 + nt][j] += fast_tanh(c[nt][j]);
        }

        __syncthreads();                 // all reads of A/W done
        if (layer < 2) {
            fill_tile_async(sb + SM_W, (const uint4*)(g_wt[layer + 1]), tid);
            CP_COMMIT();
            CP_WAIT0();                  // waits W(next) and A(next)
            __syncthreads();
            cur ^= 1;
        }
    }

    // single write: out = ent + acc
    int m0 = row0 + wid * 16 + (lane >> 2);
    int nb = (lane & 3) * 2;
    #pragma unroll
    for (int nt = 0; nt < 16; nt++) {
        int n = nt * 8 + nb;
        if (m0 < N_ENT) {
            const float2* ep = (const float2*)(ent + (size_t)m0 * H + n);
            float2 v0 = *ep;
            v0.x += acc[nt][0];
            v0.y += acc[nt][1];
            *(float2*)(out + (size_t)m0 * H + n) = v0;
        }
        if (m0 + 8 < N_ENT) {
            const float2* ep = (const float2*)(ent + (size_t)(m0 + 8) * H + n);
            float2 v1 = *ep;
            v1.x += acc[nt][2];
            v1.y += acc[nt][3];
            *(float2*)(out + (size_t)(m0 + 8) * H + n) = v1;
        }
    }
}

// ================= launch =================
extern "C" void kernel_launch(void* const* d_in, const int* in_sizes, int n_in,
                              void* d_out, int out_size) {
    const float* ent    = (const float*)d_in[0];
    const float* rel    = (const float*)d_in[1];
    const float* w_edge = (const float*)d_in[2];
    const float* w_node = (const float*)d_in[3];
    const float* w_comp = (const float*)d_in[4];
    const int*   src    = (const int*)d_in[5];
    const int*   dst    = (const int*)d_in[6];
    const int*   rid    = (const int*)d_in[7];
    float*       out    = (float*)d_out;

    cudaFuncSetAttribute(k_gemm3, cudaFuncAttributeMaxDynamicSharedMemorySize, SM_TOT);

    // g_deg/g_base are zero at load and re-zeroed by k_gemm3 every call.
    k_hist <<<(N_EDGE + 255) / 256, 256>>>(dst);             // launch 1 (rank too)
    k_alloc<<<196, 256>>>(w_edge, w_node, w_comp);           // launch 2
    k_fill <<<(N_EDGE + 255) / 256, 256>>>(src, dst, rid);   // launch 3 (no atomics)
    k_agg  <<<N_ENT / 8, 256>>>(ent, rel);                   // launch 4 <- profiled
    k_gemm3<<<N_PAD / 128, 256, SM_TOT>>>(ent, out);         // launch 5
}

// round 13
// speedup vs baseline: 1.3130x; 1.0349x over previous
#include <cuda_runtime.h>
#include <cuda_fp16.h>
#include <math.h>
#include <stdint.h>

#define N_ENT  50000
#define N_PAD  50048           // 391 * 128
#define N_EDGE 500000
#define H      128

// ================= scratch (static __device__, zero-init at load) =========
// g_deg and g_base are re-zeroed by k_gemm3 at the end of every call.
__device__ int      g_deg[N_ENT];
__device__ int      g_off[N_ENT];
__device__ int      g_base;
__device__ int      g_rank[N_EDGE];      // edge rank within dst segment (from k_hist)
__device__ unsigned g_pk[N_EDGE];        // packed src*512 + rel_id
__device__ __align__(16) __half g_a[3][N_PAD * H];   // neigh fp16 (pad rows stay 0)
__device__ __align__(16) __half g_wt[3][H * H];      // W^T fp16 (h-major rows)

// ================= helpers =================
__device__ __forceinline__ float dot4(float4 a, float4 b) {
    return a.x * b.x + a.y * b.y + a.z * b.z + a.w * b.w;
}
__device__ __forceinline__ float fast_tanh(float x) {
    float e = __expf(2.f * x);
    return 1.f - __fdividef(2.f, e + 1.f);
}
__device__ __forceinline__ uint32_t smem_u32(const void* p) {
    uint32_t a;
    asm("{ .reg .u64 t; cvta.to.shared.u64 t, %1; cvt.u32.u64 %0, t; }" : "=r"(a) : "l"(p));
    return a;
}
#define LDSM4(R0, R1, R2, R3, addr) \
    asm volatile("ldmatrix.sync.aligned.m8n8.x4.shared.b16 {%0,%1,%2,%3}, [%4];" \
        : "=r"(R0), "=r"(R1), "=r"(R2), "=r"(R3) : "r"(addr))
#define MMA16816(C, A0, A1, A2, A3, B0, B1) \
    asm volatile("mma.sync.aligned.m16n8k16.row.col.f32.f16.f16.f32 " \
        "{%0,%1,%2,%3}, {%4,%5,%6,%7}, {%8,%9}, {%0,%1,%2,%3};" \
        : "+f"((C)[0]), "+f"((C)[1]), "+f"((C)[2]), "+f"((C)[3]) \
        : "r"(A0), "r"(A1), "r"(A2), "r"(A3), "r"(B0), "r"(B1))
#define CP16(sm_addr, gptr) \
    asm volatile("cp.async.cg.shared.global [%0], [%1], 16;" :: "r"(sm_addr), "l"(gptr))
#define CP_COMMIT() asm volatile("cp.async.commit_group;")
#define CP_WAIT0()  asm volatile("cp.async.wait_group 0;")

// ================= K1: degree histogram; atomic return = segment rank ====
__global__ void k_hist(const int* __restrict__ dst) {
    int e = blockIdx.x * blockDim.x + threadIdx.x;
    if (e < N_EDGE) g_rank[e] = atomicAdd(&g_deg[dst[e]], 1);
}

// ================= K2: parallel CSR offsets + W^T fp16 prep ==============
__global__ void __launch_bounds__(256)
k_alloc(const float* __restrict__ we, const float* __restrict__ wn,
        const float* __restrict__ wc) {
    int t = threadIdx.x;
    int i = blockIdx.x * 256 + t;

    if (i < 3 * H * H) {
        int l = i >> 14, r = i & 16383;
        int k = r >> 7, h = r & 127;
        const float* W = (l == 0) ? we : (l == 1) ? wn : wc;
        g_wt[l][h * H + k] = __float2half(W[k * H + h]);
    }

    int d = (i < N_ENT) ? g_deg[i] : 0;
    int lane = t & 31, wid = t >> 5;
    int x = d;
    #pragma unroll
    for (int o = 1; o < 32; o <<= 1) {
        int y = __shfl_up_sync(0xffffffffu, x, o);
        if (lane >= o) x += y;
    }
    __shared__ int wsum[8];
    __shared__ int blockbase;
    if (lane == 31) wsum[wid] = x;
    __syncthreads();
    if (t == 0) {
        int run = 0;
        #pragma unroll
        for (int k = 0; k < 8; k++) { int v = wsum[k]; wsum[k] = run; run += v; }
        blockbase = atomicAdd(&g_base, run);
    }
    __syncthreads();
    if (i < N_ENT) g_off[i] = blockbase + wsum[wid] + (x - d);
}

// ================= K3: atomic-free edge scatter ==========================
__global__ void k_fill(const int* __restrict__ src, const int* __restrict__ dst,
                       const int* __restrict__ rid) {
    int e = blockIdx.x * blockDim.x + threadIdx.x;
    if (e >= N_EDGE) return;
    int p = g_off[dst[e]] + g_rank[e];
    g_pk[p] = (unsigned)src[e] * 512u + (unsigned)rid[e];
}

// ================= K4: warp-per-node agg, butterfly multi-reduce =========
// The 4 dot reductions (dnA,deA,dnB,deB) share one folded butterfly:
// xor16 folds A|B, xor8 folds dn|de, xor4/2/1 allreduce within 8 lanes.
// One __expf per lane on the group total, then 4 index-SHFL broadcasts.
__global__ void __launch_bounds__(256)
k_agg(const float* __restrict__ ent, const float* __restrict__ rel) {
    const unsigned F = 0xffffffffu;
    int w    = (blockIdx.x * blockDim.x + threadIdx.x) >> 5;
    int lane = threadIdx.x & 31;
    if (w >= N_ENT) return;

    float4 v = ((const float4*)(ent + (size_t)w * H))[lane];
    int start = g_off[w];
    int end   = start + g_deg[w];

    float4 a0 = make_float4(0.f, 0.f, 0.f, 0.f), a1 = a0, a2 = a0;
    float s0 = 0.f, s1 = 0.f, s2 = 0.f;

    unsigned nA = 0, nB = 0;
    if (start < end) {
        nA = g_pk[start];
        nB = (start + 1 < end) ? g_pk[start + 1] : nA;
    }
    for (int i = start; i < end; i += 2) {
        unsigned pA = nA, pB = nB;
        int hasB = (i + 1 < end);
        int j = i + 2;
        if (j < end) {
            nA = g_pk[j];
            nB = (j + 1 < end) ? g_pk[j + 1] : nA;
        }

        float4 uA = ((const float4*)(ent + (size_t)(pA >> 9) * H))[lane];
        float4 qA = ((const float4*)(rel + (size_t)(pA & 511u) * H))[lane];
        float4 uB = ((const float4*)(ent + (size_t)(pB >> 9) * H))[lane];
        float4 qB = ((const float4*)(rel + (size_t)(pB & 511u) * H))[lane];

        float dnA = dot4(uA, v), deA = dot4(qA, v);
        float dnB = dot4(uB, v), deB = dot4(qB, v);

        // --- folded butterfly: 9 SHFL + 9 ADD + 3 SEL for all 4 totals ---
        float rA  = dnA + __shfl_xor_sync(F, dnA, 16);   // bit4 folded
        float rAe = deA + __shfl_xor_sync(F, deA, 16);
        float rB  = dnB + __shfl_xor_sync(F, dnB, 16);
        float rBe = deB + __shfl_xor_sync(F, deB, 16);
        float x = (lane & 16) ? rB  : rA;                // halves: A | B
        float y = (lane & 16) ? rBe : rAe;
        float sx = x + __shfl_xor_sync(F, x, 8);         // bit3 folded
        float sy = y + __shfl_xor_sync(F, y, 8);
        float zz = (lane & 8) ? sy : sx;                 // octets: dn | de
        zz += __shfl_xor_sync(F, zz, 4);
        zz += __shfl_xor_sync(F, zz, 2);
        zz += __shfl_xor_sync(F, zz, 1);
        // lanes 0-7: dnA | 8-15: deA | 16-23: dnB | 24-31: deB (totals)
        float ev = __expf(zz);                           // one MUFU path per lane
        float nAx = __shfl_sync(F, ev, 0);
        float eA  = __shfl_sync(F, ev, 8);
        float nBx = __shfl_sync(F, ev, 16);
        float eB  = __shfl_sync(F, ev, 24);

        float cA = eA * nAx;
        s0 += eA; s1 += nAx; s2 += cA;
        a0.x += eA * qA.x; a0.y += eA * qA.y; a0.z += eA * qA.z; a0.w += eA * qA.w;
        a1.x += nAx * uA.x; a1.y += nAx * uA.y; a1.z += nAx * uA.z; a1.w += nAx * uA.w;
        a2.x += cA * (uA.x + qA.x); a2.y += cA * (uA.y + qA.y);
        a2.z += cA * (uA.z + qA.z); a2.w += cA * (uA.w + qA.w);
        if (hasB) {
            float cB = eB * nBx;
            s0 += eB; s1 += nBx; s2 += cB;
            a0.x += eB * qB.x; a0.y += eB * qB.y; a0.z += eB * qB.z; a0.w += eB * qB.w;
            a1.x += nBx * uB.x; a1.y += nBx * uB.y; a1.z += nBx * uB.z; a1.w += nBx * uB.w;
            a2.x += cB * (uB.x + qB.x); a2.y += cB * (uB.y + qB.y);
            a2.z += cB * (uB.z + qB.z); a2.w += cB * (uB.w + qB.w);
        }
    }

    float i0 = (end > start) ? 1.f / s0 : 0.f;
    float i1 = (end > start) ? 1.f / s1 : 0.f;
    float i2 = (end > start) ? 1.f / s2 : 0.f;
    size_t off = (size_t)w * H + lane * 4;
    *(__half2*)&g_a[0][off]     = __floats2half2_rn(a0.x * i0, a0.y * i0);
    *(__half2*)&g_a[0][off + 2] = __floats2half2_rn(a0.z * i0, a0.w * i0);
    *(__half2*)&g_a[1][off]     = __floats2half2_rn(a1.x * i1, a1.y * i1);
    *(__half2*)&g_a[1][off + 2] = __floats2half2_rn(a1.z * i1, a1.w * i1);
    *(__half2*)&g_a[2][off]     = __floats2half2_rn(a2.x * i2, a2.y * i2);
    *(__half2*)&g_a[2][off + 2] = __floats2half2_rn(a2.z * i2, a2.w * i2);
}

// ================= K5: fp16 HMMA GEMM, cross-layer register accumulator ===
#define PITCH    272
#define TILE_B   (128 * PITCH)          // 34816
#define SM_A0    0
#define SM_A1    TILE_B
#define SM_W     (2 * TILE_B)
#define SM_TOT   (3 * TILE_B)           // 104448

__device__ __forceinline__ void fill_tile_async(uint32_t smbase, const uint4* src, int tid) {
    #pragma unroll
    for (int i = 0; i < 8; i++) {
        int idx = i * 256 + tid;
        int row = idx >> 4, ch = idx & 15;
        CP16(smbase + (uint32_t)(row * PITCH + ch * 16), src + idx);
    }
}

__global__ void __launch_bounds__(256, 2)
k_gemm3(const float* __restrict__ ent, float* __restrict__ out) {
    extern __shared__ char sm[];
    uint32_t sb = smem_u32(sm);
    int tid  = threadIdx.x;
    int wid  = tid >> 5;
    int lane = tid & 31;
    int row0 = blockIdx.x * 128;

    // re-zero scratch for next graph replay (dead after k_agg)
    int z = blockIdx.x * 256 + tid;
    if (z < N_ENT) g_deg[z] = 0;
    if (z == N_ENT) g_base = 0;

    int q = lane >> 3, r = lane & 7;
    uint32_t a_off = (uint32_t)((wid * 16 + r + (q & 1) * 8) * PITCH + (q >> 1) * 16);
    uint32_t b_off = (uint32_t)(((q >> 1) * 8 + r) * PITCH + (q & 1) * 16);

    fill_tile_async(sb + SM_A0, (const uint4*)(g_a[0] + (size_t)row0 * H), tid);
    fill_tile_async(sb + SM_W,  (const uint4*)(g_wt[0]), tid);
    CP_COMMIT();
    CP_WAIT0();
    __syncthreads();

    float acc[16][4];
    #pragma unroll
    for (int nt = 0; nt < 16; nt++)
        #pragma unroll
        for (int j = 0; j < 4; j++) acc[nt][j] = 0.f;

    int cur = 0;
    for (int layer = 0; layer < 3; layer++) {
        if (layer < 2) {
            fill_tile_async(sb + (cur ? SM_A0 : SM_A1),
                            (const uint4*)(g_a[layer + 1] + (size_t)row0 * H), tid);
            CP_COMMIT();
        }

        uint32_t ab = sb + (cur ? SM_A1 : SM_A0) + a_off;
        uint32_t bb = sb + SM_W + b_off;

        #pragma unroll
        for (int nh = 0; nh < 2; nh++) {
            float c[8][4];
            #pragma unroll
            for (int nt = 0; nt < 8; nt++)
                #pragma unroll
                for (int j = 0; j < 4; j++) c[nt][j] = 0.f;

            #pragma unroll
            for (int ks = 0; ks < 8; ks++) {
                uint32_t aa0, aa1, aa2, aa3;
                LDSM4(aa0, aa1, aa2, aa3, ab + ks * 32);
                #pragma unroll
                for (int np = 0; np < 4; np++) {
                    uint32_t b0, b1, b2, b3;
                    LDSM4(b0, b1, b2, b3,
                          bb + (nh * 4 + np) * (16 * PITCH) + ks * 32);
                    MMA16816(c[np * 2],     aa0, aa1, aa2, aa3, b0, b1);
                    MMA16816(c[np * 2 + 1], aa0, aa1, aa2, aa3, b2, b3);
                }
            }
            #pragma unroll
            for (int nt = 0; nt < 8; nt++)
                #pragma unroll
                for (int j = 0; j < 4; j++)
                    acc[nh * 8 + nt][j] += fast_tanh(c[nt][j]);
        }

        __syncthreads();
        if (layer < 2) {
            fill_tile_async(sb + SM_W, (const uint4*)(g_wt[layer + 1]), tid);
            CP_COMMIT();
            CP_WAIT0();
            __syncthreads();
            cur ^= 1;
        }
    }

    // single write: out = ent + acc
    int m0 = row0 + wid * 16 + (lane >> 2);
    int nb = (lane & 3) * 2;
    #pragma unroll
    for (int nt = 0; nt < 16; nt++) {
        int n = nt * 8 + nb;
        if (m0 < N_ENT) {
            const float2* ep = (const float2*)(ent + (size_t)m0 * H + n);
            float2 v0 = *ep;
            v0.x += acc[nt][0];
            v0.y += acc[nt][1];
            *(float2*)(out + (size_t)m0 * H + n) = v0;
        }
        if (m0 + 8 < N_ENT) {
            const float2* ep = (const float2*)(ent + (size_t)(m0 + 8) * H + n);
            float2 v1 = *ep;
            v1.x += acc[nt][2];
            v1.y += acc[nt][3];
            *(float2*)(out + (size_t)(m0 + 8) * H + n) = v1;
        }
    }
}

// ================= launch =================
extern "C" void kernel_launch(void* const* d_in, const int* in_sizes, int n_in,
                              void* d_out, int out_size) {
    const float* ent    = (const float*)d_in[0];
    const float* rel    = (const float*)d_in[1];
    const float* w_edge = (const float*)d_in[2];
    const float* w_node = (const float*)d_in[3];
    const float* w_comp = (const float*)d_in[4];
    const int*   src    = (const int*)d_in[5];
    const int*   dst    = (const int*)d_in[6];
    const int*   rid    = (const int*)d_in[7];
    float*       out    = (float*)d_out;

    cudaFuncSetAttribute(k_gemm3, cudaFuncAttributeMaxDynamicSharedMemorySize, SM_TOT);

    // g_deg/g_base are zero at load and re-zeroed by k_gemm3 every call.
    k_hist <<<(N_EDGE + 255) / 256, 256>>>(dst);             // launch 1 (rank too)
    k_alloc<<<196, 256>>>(w_edge, w_node, w_comp);           // launch 2
    k_fill <<<(N_EDGE + 255) / 256, 256>>>(src, dst, rid);   // launch 3 (no atomics)
    k_agg  <<<N_ENT / 8, 256>>>(ent, rel);                   // launch 4 <- profiled
    k_gemm3<<<N_PAD / 128, 256, SM_TOT>>>(ent, out);         // launch 5
}